// round 13
// baseline (speedup 1.0000x reference)
#include <cuda_runtime.h>
#include <cuda_fp16.h>
#include <cstdint>
#include <math.h>

// ---------------------------------------------------------------------------
// Problem dims (fixed)
// ---------------------------------------------------------------------------
constexpr int BATCH = 4;
constexpr int TLEN  = 2048;
constexpr int HD    = 2048;                  // N = K = 2048
constexpr int MROWS = BATCH * TLEN;          // 8192
constexpr size_t TOT = (size_t)MROWS * HD;   // 16,777,216
constexpr int CH    = BATCH * HD;            // 8192 scan channels
constexpr int SEG   = 32;
constexpr int SEGLEN = TLEN / SEG;           // 64

// GEMM tiling: CTA 128x128x64, 4 warps (2M x 2N), warp tile 64x64, 3 stages,
// 2 CTAs/SM (smem 110.6 KB)
constexpr int GEMM_THREADS = 128;
constexpr int BM = 128;
constexpr int BN = 128;
constexpr int BK = 64;
constexpr int NITER = HD / BK;               // 32
constexpr int STAGES = 3;
constexpr int PITCH = 144;                   // 64 fp16 = 128B data + 16B pad
constexpr int PLANE = 128 * PITCH;           // 18432
constexpr int STAGE_BYTES = 2 * PLANE;       // A + B = 36864
constexpr int SMEM_GEMM = STAGES * STAGE_BYTES;  // 110592

// ---------------------------------------------------------------------------
// Scratch (device globals: allocation-free per harness rules)
// ---------------------------------------------------------------------------
__device__ __align__(256) __half g_ak[TOT];   // key-mix (reused as p = r*rwkv)
__device__ __align__(256) __half g_av[TOT];
__device__ __align__(256) __half g_ar[TOT];   // receptance mix (GEMM input)
__device__ __align__(256) __half g_rh[TOT];   // r = sigmoid(...) fp16
__device__ __align__(256) float g_k[TOT];
__device__ __align__(256) float g_v[TOT];
// transposed weights: [N=2048, K=2048] fp16, K-major
__device__ __align__(256) __half g_wk[HD * HD];
__device__ __align__(256) __half g_wv[HD * HD];
__device__ __align__(256) __half g_wr[HD * HD];
__device__ __align__(256) __half g_wo[HD * HD];
// WKV segment summaries / prefixes: [SEG][CH]
__device__ float g_sn[SEG * CH];
__device__ float g_sd[SEG * CH];
__device__ float g_sm[SEG * CH];
__device__ float g_pn[SEG * CH];
__device__ float g_pd[SEG * CH];
__device__ float g_pm[SEG * CH];

// ---------------------------------------------------------------------------
// PTX helpers (base sm_103 target: cp.async, ldmatrix, mma.sync)
// ---------------------------------------------------------------------------
__device__ __forceinline__ uint32_t smem_u32(const void* p) {
    uint32_t a;
    asm("{ .reg .u64 t; cvta.to.shared.u64 t, %1; cvt.u32.u64 %0, t; }"
        : "=r"(a) : "l"(p));
    return a;
}

__device__ __forceinline__ void cp_async16(uint32_t s, const void* g) {
    asm volatile("cp.async.cg.shared.global [%0], [%1], 16;" :: "r"(s), "l"(g));
}
__device__ __forceinline__ void cp_commit() {
    asm volatile("cp.async.commit_group;" ::: "memory");
}
template <int N>
__device__ __forceinline__ void cp_wait() {
    asm volatile("cp.async.wait_group %0;" :: "n"(N) : "memory");
}

__device__ __forceinline__ void ldsm_x4(uint32_t* r, uint32_t addr) {
    asm volatile("ldmatrix.sync.aligned.m8n8.x4.shared.b16 {%0,%1,%2,%3}, [%4];"
        : "=r"(r[0]), "=r"(r[1]), "=r"(r[2]), "=r"(r[3]) : "r"(addr));
}

// mma.sync m16n8k16 fp16 -> fp32, D += A*B
__device__ __forceinline__ void mma16816(float* d, const uint32_t* a,
                                         uint32_t b0, uint32_t b1) {
    asm volatile(
        "mma.sync.aligned.m16n8k16.row.col.f32.f16.f16.f32 "
        "{%0,%1,%2,%3}, {%4,%5,%6,%7}, {%8,%9}, {%0,%1,%2,%3};"
        : "+f"(d[0]), "+f"(d[1]), "+f"(d[2]), "+f"(d[3])
        : "r"(a[0]), "r"(a[1]), "r"(a[2]), "r"(a[3]), "r"(b0), "r"(b1));
}

__device__ __forceinline__ uint32_t pack2h(__half a, __half b) {
    __half2 t(a, b);
    return *(uint32_t*)&t;
}

// ---------------------------------------------------------------------------
// Fused prep: z 0..3 = weight transpose W[K,N] fp32 -> T[N,K] fp16,
//             z 4..7 = time-shift + three mixes (quarter slices).
// ---------------------------------------------------------------------------
__global__ void prep_kernel(const float* __restrict__ W0,
                            const float* __restrict__ W1,
                            const float* __restrict__ W2,
                            const float* __restrict__ W3,
                            __half* __restrict__ T0,
                            __half* __restrict__ T1,
                            __half* __restrict__ T2,
                            __half* __restrict__ T3,
                            const float* __restrict__ hidden,
                            const float* __restrict__ tmk,
                            const float* __restrict__ tmv,
                            const float* __restrict__ tmr) {
    int z = blockIdx.z;
    if (z < 4) {
        const float* W;
        __half* T;
        switch (z) {
            case 0: W = W0; T = T0; break;
            case 1: W = W1; T = T1; break;
            case 2: W = W2; T = T2; break;
            default: W = W3; T = T3; break;
        }
        __shared__ float tile[32][33];
        int tx = threadIdx.x & 31;
        int ty0 = threadIdx.x >> 5;          // 0..7
        int bx = blockIdx.x * 32;            // n base
        int by = blockIdx.y * 32;            // k base
        #pragma unroll
        for (int i = 0; i < 32; i += 8)
            tile[ty0 + i][tx] = W[(size_t)(by + ty0 + i) * HD + bx + tx];
        __syncthreads();
        #pragma unroll
        for (int i = 0; i < 32; i += 8)
            T[(size_t)(bx + ty0 + i) * HD + by + tx] =
                __float2half_rn(tile[tx][ty0 + i]);
        return;
    }

    // mix path: flattened float4 index over TOT/4 elements
    int cta = (z - 4) * 4096 + blockIdx.y * 64 + blockIdx.x;
    int idx = cta * 256 + threadIdx.x;        // float4 index
    constexpr int HV = HD / 4;
    int row = idx / HV;
    int hv  = idx % HV;
    bool hasPrev = (row % TLEN) != 0;

    const float4* h4 = (const float4*)hidden;
    float4 cur  = h4[idx];
    float4 prev = hasPrev ? h4[idx - HV] : make_float4(0.f, 0.f, 0.f, 0.f);

    float4 mk = ((const float4*)tmk)[hv];
    float4 mv = ((const float4*)tmv)[hv];
    float4 mr = ((const float4*)tmr)[hv];

    float c[4] = {cur.x, cur.y, cur.z, cur.w};
    float p[4] = {prev.x, prev.y, prev.z, prev.w};
    float k_[4] = {mk.x, mk.y, mk.z, mk.w};
    float v_[4] = {mv.x, mv.y, mv.z, mv.w};
    float r_[4] = {mr.x, mr.y, mr.z, mr.w};

    __half hk[4], hv_[4], hr[4];
    #pragma unroll
    for (int i = 0; i < 4; i++) {
        hk[i]  = __float2half_rn(p[i] + k_[i] * (c[i] - p[i]));
        hv_[i] = __float2half_rn(p[i] + v_[i] * (c[i] - p[i]));
        hr[i]  = __float2half_rn(p[i] + r_[i] * (c[i] - p[i]));
    }

    uint2 out;
    out.x = pack2h(hk[0], hk[1]);  out.y = pack2h(hk[2], hk[3]);
    ((uint2*)g_ak)[idx] = out;
    out.x = pack2h(hv_[0], hv_[1]); out.y = pack2h(hv_[2], hv_[3]);
    ((uint2*)g_av)[idx] = out;
    out.x = pack2h(hr[0], hr[1]);  out.y = pack2h(hr[2], hr[3]);
    ((uint2*)g_ar)[idx] = out;
}

// ---------------------------------------------------------------------------
// fp16 mma.sync GEMM:  C[M,HD] = A[M,HD] @ Bt[HD,HD]^T  (Bt is [N,K] K-major)
// CTA 128x128x64, 4 warps (2M x 2N), warp tile 64x64, 3 stages, 2 CTAs/SM.
// blockIdx.z selects the (A, B, C) triple. z == sigz: sigmoid epilogue AND
// fp16 output (C pointer reinterpreted as __half*).
// ---------------------------------------------------------------------------
__global__ void __launch_bounds__(GEMM_THREADS, 2)
gemm_f16(const __half* __restrict__ A0, const __half* __restrict__ A1,
         const __half* __restrict__ A2,
         const __half* __restrict__ B0, const __half* __restrict__ B1,
         const __half* __restrict__ B2,
         float* __restrict__ C0, float* __restrict__ C1, float* __restrict__ C2,
         int sigz) {
    extern __shared__ char smem[];
    uint32_t sbase = smem_u32(smem);

    const __half* A;
    const __half* B;
    float* C;
    int z = blockIdx.z;
    if (z == 0)      { A = A0; B = B0; C = C0; }
    else if (z == 1) { A = A1; B = B1; C = C1; }
    else             { A = A2; B = B2; C = C2; }
    bool sig = (z == sigz);

    int tid = threadIdx.x;
    int wid = tid >> 5;
    int lid = tid & 31;
    int mBase = blockIdx.y * BM;
    int nBase = blockIdx.x * BN;

    int wm = (wid & 1) * 64;       // warp M offset
    int wn = (wid >> 1) * 64;      // warp N offset

    // gmem->smem: A 1024 chunks(16B) + B 1024 chunks, 128 threads, 16/thread
    auto load_stage = [&](int buf, int k0) {
        uint32_t st = sbase + buf * STAGE_BYTES;
        #pragma unroll
        for (int i = 0; i < 8; i++) {
            int id = tid + i * GEMM_THREADS;
            int r = id >> 3, c = id & 7;
            uint32_t so = (uint32_t)(r * PITCH + c * 16);
            cp_async16(st + so,         A + (size_t)(mBase + r) * HD + k0 + c * 8);
            cp_async16(st + PLANE + so, B + (size_t)(nBase + r) * HD + k0 + c * 8);
        }
    };

    float acc[4][8][4];   // [fm][fn][4] = 128 regs
    #pragma unroll
    for (int a = 0; a < 4; a++)
        #pragma unroll
        for (int b = 0; b < 8; b++)
            #pragma unroll
            for (int c = 0; c < 4; c++) acc[a][b][c] = 0.f;

    load_stage(0, 0);
    cp_commit();
    load_stage(1, BK);
    cp_commit();

    // A ldmatrix lane address: rows m = wm + (lid&15), byte (lid>>4)*16
    uint32_t aLane = (uint32_t)((wm + (lid & 15)) * PITCH + (lid >> 4) * 16);
    // B ldmatrix lane address (pair p covers fn = 2p, 2p+1)
    uint32_t bLane = (uint32_t)((wn + (lid & 7) + ((lid >> 3) & 1) * 8) * PITCH
                                + (lid >> 4) * 16);

    for (int s = 0; s < NITER; s++) {
        cp_wait<STAGES - 2>();
        __syncthreads();

        if (s + STAGES - 1 < NITER) {
            load_stage((s + STAGES - 1) % STAGES, (s + STAGES - 1) * BK);
            cp_commit();
        }

        uint32_t st = sbase + (s % STAGES) * STAGE_BYTES;
        uint32_t aA = st + aLane;
        uint32_t bB = st + PLANE + bLane;

        #pragma unroll
        for (int ks = 0; ks < 4; ks++) {     // 4 x k16 per stage
            uint32_t ah[4][4], bb[4][4];
            #pragma unroll
            for (int fm = 0; fm < 4; fm++)
                ldsm_x4(ah[fm], aA + fm * (16 * PITCH) + ks * 32);
            #pragma unroll
            for (int p = 0; p < 4; p++)      // each covers fn = 2p, 2p+1
                ldsm_x4(bb[p], bB + p * (16 * PITCH) + ks * 32);
            #pragma unroll
            for (int fm = 0; fm < 4; fm++)
                #pragma unroll
                for (int p = 0; p < 4; p++) {
                    mma16816(acc[fm][2 * p],     ah[fm], bb[p][0], bb[p][2]);
                    mma16816(acc[fm][2 * p + 1], ah[fm], bb[p][1], bb[p][3]);
                }
        }
    }

    // epilogue
    int gid = lid >> 2, tig = lid & 3;
    if (sig) {
        __half* Ch = (__half*)C;
        #pragma unroll
        for (int fm = 0; fm < 4; fm++) {
            int row0 = mBase + wm + fm * 16 + gid;
            #pragma unroll
            for (int fn = 0; fn < 8; fn++) {
                int col = nBase + wn + fn * 8 + tig * 2;
                float s0 = 1.f / (1.f + __expf(-acc[fm][fn][0]));
                float s1 = 1.f / (1.f + __expf(-acc[fm][fn][1]));
                float s2 = 1.f / (1.f + __expf(-acc[fm][fn][2]));
                float s3 = 1.f / (1.f + __expf(-acc[fm][fn][3]));
                *(__half2*)(Ch + (size_t)row0 * HD + col) =
                    __half2(__float2half_rn(s0), __float2half_rn(s1));
                *(__half2*)(Ch + (size_t)(row0 + 8) * HD + col) =
                    __half2(__float2half_rn(s2), __float2half_rn(s3));
            }
        }
    } else {
        #pragma unroll
        for (int fm = 0; fm < 4; fm++) {
            int row0 = mBase + wm + fm * 16 + gid;
            #pragma unroll
            for (int fn = 0; fn < 8; fn++) {
                int col = nBase + wn + fn * 8 + tig * 2;
                float2 v0 = make_float2(acc[fm][fn][0], acc[fm][fn][1]);
                float2 v1 = make_float2(acc[fm][fn][2], acc[fm][fn][3]);
                *(float2*)(C + (size_t)row0 * HD + col) = v0;
                *(float2*)(C + (size_t)(row0 + 8) * HD + col) = v1;
            }
        }
    }
}

// ---------------------------------------------------------------------------
// WKV 3-phase segmented scan. Channel ch = b*HD + d. idx = seg*CH + ch.
// SEG=32 segments of 64 steps: 262144 threads => latency fully hidden.
// ---------------------------------------------------------------------------
__global__ void wkv_passA(const float* __restrict__ time_decay) {
    int idx = blockIdx.x * blockDim.x + threadIdx.x;   // 0..SEG*CH-1
    int d = idx % HD;
    int bc = idx / HD;
    int b = bc % BATCH;
    int seg = bc / BATCH;

    float td = -__expf(time_decay[d]);
    float num = 0.f, den = 0.f, mx = -1e38f;
    size_t base = (size_t)b * TLEN * HD + d;

    for (int t = seg * SEGLEN; t < (seg + 1) * SEGLEN; t++) {
        size_t off = base + (size_t)t * HD;
        float kt = g_k[off];
        float vt = g_v[off];
        float mfs = fmaxf(mx + td, kt);
        float e1s = __expf(mx + td - mfs);
        float e2s = __expf(kt - mfs);
        num = e1s * num + e2s * vt;
        den = e1s * den + e2s;
        mx  = mfs;
    }
    g_sn[idx] = num;
    g_sd[idx] = den;
    g_sm[idx] = mx;
}

__global__ void wkv_passB(const float* __restrict__ time_decay) {
    int ch = blockIdx.x * blockDim.x + threadIdx.x;   // 0..CH-1
    int d = ch % HD;
    float td = -__expf(time_decay[d]);
    float decL = td * (float)SEGLEN;

    float n0 = 0.f, d0 = 0.f, m0 = -1e38f;
    #pragma unroll
    for (int s = 0; s < SEG; s++) {
        int o = s * CH + ch;
        g_pn[o] = n0;
        g_pd[o] = d0;
        g_pm[o] = m0;
        float ns = g_sn[o], ds = g_sd[o], ms = g_sm[o];
        float mA = m0 + decL;
        float mn = fmaxf(ms, mA);
        float ea = __expf(mA - mn);
        float eb = __expf(ms - mn);
        n0 = ea * n0 + eb * ns;
        d0 = ea * d0 + eb * ds;
        m0 = mn;
    }
}

__global__ void wkv_passC(const float* __restrict__ time_decay,
                          const float* __restrict__ time_first) {
    int idx = blockIdx.x * blockDim.x + threadIdx.x;
    int d = idx % HD;
    int bc = idx / HD;
    int b = bc % BATCH;
    int seg = bc / BATCH;

    float td = -__expf(time_decay[d]);
    float tf = time_first[d];

    float num = g_pn[idx], den = g_pd[idx], mx = g_pm[idx];
    size_t base = (size_t)b * TLEN * HD + d;

    for (int t = seg * SEGLEN; t < (seg + 1) * SEGLEN; t++) {
        size_t off = base + (size_t)t * HD;
        float kt = g_k[off];
        float vt = g_v[off];
        float rt = __half2float(g_rh[off]);

        float mfo = fmaxf(mx, kt + tf);
        float e1  = __expf(mx - mfo);
        float e2  = __expf(kt + tf - mfo);
        float out = (e1 * num + e2 * vt) / (e1 * den + e2);

        float mfs = fmaxf(mx + td, kt);
        float e1s = __expf(mx + td - mfs);
        float e2s = __expf(kt - mfs);
        num = e1s * num + e2s * vt;
        den = e1s * den + e2s;
        mx  = mfs;

        g_ak[off] = __float2half_rn(out * rt);
    }
}

// ---------------------------------------------------------------------------
// Launch
// ---------------------------------------------------------------------------
extern "C" void kernel_launch(void* const* d_in, const int* in_sizes, int n_in,
                              void* d_out, int out_size) {
    const float* hidden = (const float*)d_in[0];
    const float* time_decay = (const float*)d_in[1];
    const float* time_first = (const float*)d_in[2];
    const float* tmk = (const float*)d_in[3];
    const float* tmv = (const float*)d_in[4];
    const float* tmr = (const float*)d_in[5];
    const float* Wk = (const float*)d_in[6];
    const float* Wv = (const float*)d_in[7];
    const float* Wr = (const float*)d_in[8];
    const float* Wo = (const float*)d_in[9];

    __half *ak, *av, *ar, *rh, *wk, *wv, *wr, *wo;
    float *kb, *vb;
    cudaGetSymbolAddress((void**)&ak, g_ak);
    cudaGetSymbolAddress((void**)&av, g_av);
    cudaGetSymbolAddress((void**)&ar, g_ar);
    cudaGetSymbolAddress((void**)&rh, g_rh);
    cudaGetSymbolAddress((void**)&wk, g_wk);
    cudaGetSymbolAddress((void**)&wv, g_wv);
    cudaGetSymbolAddress((void**)&wr, g_wr);
    cudaGetSymbolAddress((void**)&wo, g_wo);
    cudaGetSymbolAddress((void**)&kb, g_k);
    cudaGetSymbolAddress((void**)&vb, g_v);

    cudaFuncSetAttribute(gemm_f16, cudaFuncAttributeMaxDynamicSharedMemorySize, SMEM_GEMM);

    // 1. fused transposes (z 0..3) + mixes (z 4..7)
    prep_kernel<<<dim3(64, 64, 8), 256>>>(Wk, Wv, Wr, Wo, wk, wv, wr, wo,
                                          hidden, tmk, tmv, tmr);

    // 2. three input GEMMs in ONE launch (z==2 gets sigmoid + fp16 output)
    dim3 grid3(HD / BN, MROWS / BM, 3);   // (16, 64, 3)
    gemm_f16<<<grid3, GEMM_THREADS, SMEM_GEMM>>>(ak, av, ar, wk, wv, wr,
                                                 kb, vb, (float*)rh, 2);

    // 3. WKV segmented scan (SEG=32), writes p into g_ak
    wkv_passA<<<SEG * CH / 256, 256>>>(time_decay);
    wkv_passB<<<CH / 256, 256>>>(time_decay);
    wkv_passC<<<SEG * CH / 256, 256>>>(time_decay, time_first);

    // 4. output GEMM
    dim3 grid1(HD / BN, MROWS / BM, 1);
    gemm_f16<<<grid1, GEMM_THREADS, SMEM_GEMM>>>(ak, ak, ak, wo, wo, wo,
                                                 (float*)d_out, (float*)d_out,
                                                 (float*)d_out, -1);
}

// round 14
// speedup vs baseline: 1.0161x; 1.0161x over previous
#include <cuda_runtime.h>
#include <cuda_fp16.h>
#include <cstdint>
#include <math.h>

// ---------------------------------------------------------------------------
// Problem dims (fixed)
// ---------------------------------------------------------------------------
constexpr int BATCH = 4;
constexpr int TLEN  = 2048;
constexpr int HD    = 2048;                  // N = K = 2048
constexpr int MROWS = BATCH * TLEN;          // 8192
constexpr size_t TOT = (size_t)MROWS * HD;   // 16,777,216
constexpr int CH    = BATCH * HD;            // 8192 scan channels
constexpr int SEG   = 32;
constexpr int SEGLEN = TLEN / SEG;           // 64

// GEMM tiling: CTA 128x128x64, 8 warps (2M x 4N), warp tile 64x32, 3 stages,
// 2 CTAs/SM (smem 110.6 KB, regs <= 128)
constexpr int BM = 128;
constexpr int BN = 128;
constexpr int BK = 64;
constexpr int NITER = HD / BK;               // 32
constexpr int STAGES = 3;
constexpr int PITCH = 144;                   // 64 fp16 = 128B data + 16B pad
constexpr int PLANE = 128 * PITCH;           // 18432
constexpr int STAGE_BYTES = 2 * PLANE;       // A + B = 36864
constexpr int SMEM_GEMM = STAGES * STAGE_BYTES;  // 110592

// ---------------------------------------------------------------------------
// Scratch (device globals: allocation-free per harness rules)
// ---------------------------------------------------------------------------
__device__ __align__(256) __half g_ak[TOT];   // key-mix (reused as p = r*rwkv)
__device__ __align__(256) __half g_av[TOT];
__device__ __align__(256) __half g_ar[TOT];
__device__ __align__(256) float g_k[TOT];
__device__ __align__(256) float g_v[TOT];
__device__ __align__(256) float g_r[TOT];
// transposed weights: [N=2048, K=2048] fp16, K-major
__device__ __align__(256) __half g_wk[HD * HD];
__device__ __align__(256) __half g_wv[HD * HD];
__device__ __align__(256) __half g_wr[HD * HD];
__device__ __align__(256) __half g_wo[HD * HD];
// WKV segment summaries / prefixes: [SEG][CH]
__device__ float g_sn[SEG * CH];
__device__ float g_sd[SEG * CH];
__device__ float g_sm[SEG * CH];
__device__ float g_pn[SEG * CH];
__device__ float g_pd[SEG * CH];
__device__ float g_pm[SEG * CH];

// ---------------------------------------------------------------------------
// PTX helpers (base sm_103 target: cp.async, ldmatrix, mma.sync)
// ---------------------------------------------------------------------------
__device__ __forceinline__ uint32_t smem_u32(const void* p) {
    uint32_t a;
    asm("{ .reg .u64 t; cvta.to.shared.u64 t, %1; cvt.u32.u64 %0, t; }"
        : "=r"(a) : "l"(p));
    return a;
}

__device__ __forceinline__ void cp_async16(uint32_t s, const void* g) {
    asm volatile("cp.async.cg.shared.global [%0], [%1], 16;" :: "r"(s), "l"(g));
}
__device__ __forceinline__ void cp_commit() {
    asm volatile("cp.async.commit_group;" ::: "memory");
}
template <int N>
__device__ __forceinline__ void cp_wait() {
    asm volatile("cp.async.wait_group %0;" :: "n"(N) : "memory");
}

__device__ __forceinline__ void ldsm_x4(uint32_t* r, uint32_t addr) {
    asm volatile("ldmatrix.sync.aligned.m8n8.x4.shared.b16 {%0,%1,%2,%3}, [%4];"
        : "=r"(r[0]), "=r"(r[1]), "=r"(r[2]), "=r"(r[3]) : "r"(addr));
}

// mma.sync m16n8k16 fp16 -> fp32, D += A*B
__device__ __forceinline__ void mma16816(float* d, const uint32_t* a,
                                         uint32_t b0, uint32_t b1) {
    asm volatile(
        "mma.sync.aligned.m16n8k16.row.col.f32.f16.f16.f32 "
        "{%0,%1,%2,%3}, {%4,%5,%6,%7}, {%8,%9}, {%0,%1,%2,%3};"
        : "+f"(d[0]), "+f"(d[1]), "+f"(d[2]), "+f"(d[3])
        : "r"(a[0]), "r"(a[1]), "r"(a[2]), "r"(a[3]), "r"(b0), "r"(b1));
}

__device__ __forceinline__ uint32_t pack2h(__half a, __half b) {
    __half2 t(a, b);
    return *(uint32_t*)&t;
}

// ---------------------------------------------------------------------------
// Fused weight transposes:  W[K,N] fp32 -> T[N,K] fp16  (z selects matrix)
// ---------------------------------------------------------------------------
__global__ void transpose_half4(const float* __restrict__ W0,
                                const float* __restrict__ W1,
                                const float* __restrict__ W2,
                                const float* __restrict__ W3,
                                __half* __restrict__ T0,
                                __half* __restrict__ T1,
                                __half* __restrict__ T2,
                                __half* __restrict__ T3) {
    const float* W;
    __half* T;
    switch (blockIdx.z) {
        case 0: W = W0; T = T0; break;
        case 1: W = W1; T = T1; break;
        case 2: W = W2; T = T2; break;
        default: W = W3; T = T3; break;
    }
    __shared__ float tile[32][33];
    int tx = threadIdx.x & 31;
    int ty0 = threadIdx.x >> 5;          // 0..7
    int bx = blockIdx.x * 32;            // n base
    int by = blockIdx.y * 32;            // k base
    #pragma unroll
    for (int i = 0; i < 32; i += 8)
        tile[ty0 + i][tx] = W[(size_t)(by + ty0 + i) * HD + bx + tx];
    __syncthreads();
    #pragma unroll
    for (int i = 0; i < 32; i += 8)
        T[(size_t)(bx + ty0 + i) * HD + by + tx] = __float2half_rn(tile[tx][ty0 + i]);
}

// ---------------------------------------------------------------------------
// Time-shift + three mixes -> three fp16 planes
// ---------------------------------------------------------------------------
__global__ void mix_kernel(const float* __restrict__ hidden,
                           const float* __restrict__ tmk,
                           const float* __restrict__ tmv,
                           const float* __restrict__ tmr) {
    int idx = blockIdx.x * blockDim.x + threadIdx.x;  // float4 index
    constexpr int HV = HD / 4;
    int row = idx / HV;
    int hv  = idx % HV;
    bool hasPrev = (row % TLEN) != 0;

    const float4* h4 = (const float4*)hidden;
    float4 cur  = h4[idx];
    float4 prev = hasPrev ? h4[idx - HV] : make_float4(0.f, 0.f, 0.f, 0.f);

    float4 mk = ((const float4*)tmk)[hv];
    float4 mv = ((const float4*)tmv)[hv];
    float4 mr = ((const float4*)tmr)[hv];

    float c[4] = {cur.x, cur.y, cur.z, cur.w};
    float p[4] = {prev.x, prev.y, prev.z, prev.w};
    float k_[4] = {mk.x, mk.y, mk.z, mk.w};
    float v_[4] = {mv.x, mv.y, mv.z, mv.w};
    float r_[4] = {mr.x, mr.y, mr.z, mr.w};

    __half hk[4], hv_[4], hr[4];
    #pragma unroll
    for (int i = 0; i < 4; i++) {
        hk[i]  = __float2half_rn(p[i] + k_[i] * (c[i] - p[i]));
        hv_[i] = __float2half_rn(p[i] + v_[i] * (c[i] - p[i]));
        hr[i]  = __float2half_rn(p[i] + r_[i] * (c[i] - p[i]));
    }

    uint2 out;
    out.x = pack2h(hk[0], hk[1]);  out.y = pack2h(hk[2], hk[3]);
    ((uint2*)g_ak)[idx] = out;
    out.x = pack2h(hv_[0], hv_[1]); out.y = pack2h(hv_[2], hv_[3]);
    ((uint2*)g_av)[idx] = out;
    out.x = pack2h(hr[0], hr[1]);  out.y = pack2h(hr[2], hr[3]);
    ((uint2*)g_ar)[idx] = out;
}

// ---------------------------------------------------------------------------
// fp16 mma.sync GEMM:  C[M,HD] = A[M,HD] @ Bt[HD,HD]^T  (Bt is [N,K] K-major)
// CTA 128x128x64, 8 warps (2M x 4N), warp tile 64x32, 3 stages, 2 CTAs/SM.
// Software-pipelined A fragments (double buffer across k16 steps).
// blockIdx.z selects the (A, B, C) triple; epi sigmoid when z == sigz.
// ---------------------------------------------------------------------------
__global__ void __launch_bounds__(256, 2)
gemm_f16(const __half* __restrict__ A0, const __half* __restrict__ A1,
         const __half* __restrict__ A2,
         const __half* __restrict__ B0, const __half* __restrict__ B1,
         const __half* __restrict__ B2,
         float* __restrict__ C0, float* __restrict__ C1, float* __restrict__ C2,
         int sigz) {
    extern __shared__ char smem[];
    uint32_t sbase = smem_u32(smem);

    const __half* A;
    const __half* B;
    float* C;
    int z = blockIdx.z;
    if (z == 0)      { A = A0; B = B0; C = C0; }
    else if (z == 1) { A = A1; B = B1; C = C1; }
    else             { A = A2; B = B2; C = C2; }
    bool sig = (z == sigz);

    int tid = threadIdx.x;
    int wid = tid >> 5;
    int lid = tid & 31;
    int mBase = blockIdx.y * BM;
    int nBase = blockIdx.x * BN;

    int wm = (wid & 1) * 64;       // warp M offset
    int wn = (wid >> 1) * 32;      // warp N offset

    // gmem->smem: A 1024 chunks(16B) + B 1024 chunks = 2048, 8/thread
    auto load_stage = [&](int buf, int k0) {
        uint32_t st = sbase + buf * STAGE_BYTES;
        #pragma unroll
        for (int i = 0; i < 4; i++) {
            int id = tid + i * 256;
            int r = id >> 3, c = id & 7;
            uint32_t so = (uint32_t)(r * PITCH + c * 16);
            cp_async16(st + so,         A + (size_t)(mBase + r) * HD + k0 + c * 8);
            cp_async16(st + PLANE + so, B + (size_t)(nBase + r) * HD + k0 + c * 8);
        }
    };

    float acc[4][4][4];
    #pragma unroll
    for (int a = 0; a < 4; a++)
        #pragma unroll
        for (int b = 0; b < 4; b++)
            #pragma unroll
            for (int c = 0; c < 4; c++) acc[a][b][c] = 0.f;

    load_stage(0, 0);
    cp_commit();
    load_stage(1, BK);
    cp_commit();

    // A ldmatrix lane address: rows m = wm + (lid&15), byte (lid>>4)*16
    uint32_t aLane = (uint32_t)((wm + (lid & 15)) * PITCH + (lid >> 4) * 16);
    // B ldmatrix lane address (pair p covers fn = 2p, 2p+1)
    uint32_t bLane = (uint32_t)((wn + (lid & 7) + ((lid >> 3) & 1) * 8) * PITCH
                                + (lid >> 4) * 16);

    uint32_t ah[2][4][4];   // double-buffered A frags

    for (int s = 0; s < NITER; s++) {
        cp_wait<STAGES - 2>();
        __syncthreads();

        if (s + STAGES - 1 < NITER) {
            load_stage((s + STAGES - 1) % STAGES, (s + STAGES - 1) * BK);
            cp_commit();
        }

        uint32_t st = sbase + (s % STAGES) * STAGE_BYTES;
        uint32_t aA = st + aLane;
        uint32_t bB = st + PLANE + bLane;

        // preload A frags for ks = 0
        #pragma unroll
        for (int fm = 0; fm < 4; fm++)
            ldsm_x4(ah[0][fm], aA + fm * (16 * PITCH));

        #pragma unroll
        for (int ks = 0; ks < 4; ks++) {     // 4 x k16 per stage
            int cur = ks & 1, nxt = cur ^ 1;
            uint32_t bb[2][4];
            #pragma unroll
            for (int p = 0; p < 2; p++)      // each covers fn = 2p, 2p+1
                ldsm_x4(bb[p], bB + p * (16 * PITCH) + ks * 32);
            if (ks < 3) {                    // prefetch next ks A frags
                #pragma unroll
                for (int fm = 0; fm < 4; fm++)
                    ldsm_x4(ah[nxt][fm], aA + fm * (16 * PITCH) + (ks + 1) * 32);
            }
            #pragma unroll
            for (int fm = 0; fm < 4; fm++)
                #pragma unroll
                for (int p = 0; p < 2; p++) {
                    mma16816(acc[fm][2 * p],     ah[cur][fm], bb[p][0], bb[p][2]);
                    mma16816(acc[fm][2 * p + 1], ah[cur][fm], bb[p][1], bb[p][3]);
                }
        }
    }

    // epilogue
    int gid = lid >> 2, tig = lid & 3;
    #pragma unroll
    for (int fm = 0; fm < 4; fm++) {
        int row0 = mBase + wm + fm * 16 + gid;
        #pragma unroll
        for (int fn = 0; fn < 4; fn++) {
            int col = nBase + wn + fn * 8 + tig * 2;
            float2 v0 = make_float2(acc[fm][fn][0], acc[fm][fn][1]);
            float2 v1 = make_float2(acc[fm][fn][2], acc[fm][fn][3]);
            if (sig) {
                v0.x = 1.f / (1.f + __expf(-v0.x));
                v0.y = 1.f / (1.f + __expf(-v0.y));
                v1.x = 1.f / (1.f + __expf(-v1.x));
                v1.y = 1.f / (1.f + __expf(-v1.y));
            }
            *(float2*)(C + (size_t)row0 * HD + col) = v0;
            *(float2*)(C + (size_t)(row0 + 8) * HD + col) = v1;
        }
    }
}

// ---------------------------------------------------------------------------
// WKV 3-phase segmented scan. Channel ch = b*HD + d. idx = seg*CH + ch.
// SEG=32 segments of 64 steps: 262144 threads => latency fully hidden.
// ---------------------------------------------------------------------------
__global__ void wkv_passA(const float* __restrict__ time_decay) {
    int idx = blockIdx.x * blockDim.x + threadIdx.x;   // 0..SEG*CH-1
    int d = idx % HD;
    int bc = idx / HD;
    int b = bc % BATCH;
    int seg = bc / BATCH;

    float td = -__expf(time_decay[d]);
    float num = 0.f, den = 0.f, mx = -1e38f;
    size_t base = (size_t)b * TLEN * HD + d;

    for (int t = seg * SEGLEN; t < (seg + 1) * SEGLEN; t++) {
        size_t off = base + (size_t)t * HD;
        float kt = g_k[off];
        float vt = g_v[off];
        float mfs = fmaxf(mx + td, kt);
        float e1s = __expf(mx + td - mfs);
        float e2s = __expf(kt - mfs);
        num = e1s * num + e2s * vt;
        den = e1s * den + e2s;
        mx  = mfs;
    }
    g_sn[idx] = num;
    g_sd[idx] = den;
    g_sm[idx] = mx;
}

// Pass B: warp-parallel Kogge-Stone scan over segments. One warp per channel,
// lane = segment. Transform = (k, S): "decay k*SEGLEN steps, then merge S".
// compose(A, B) = (kA+kB, merge(S_A shifted by kB*decL, S_B)).
__global__ void wkv_passB(const float* __restrict__ time_decay) {
    int gtid = blockIdx.x * blockDim.x + threadIdx.x;
    int ch = gtid >> 5;                 // warp index = channel
    int lane = gtid & 31;               // lane = segment
    int d = ch % HD;
    float decL = -__expf(time_decay[d]) * (float)SEGLEN;

    int o = lane * CH + ch;
    float n = g_sn[o], dn = g_sd[o], m = g_sm[o];
    int k = 1;

    #pragma unroll
    for (int off = 1; off < 32; off <<= 1) {
        float on = __shfl_up_sync(0xFFFFFFFFu, n, off);
        float od = __shfl_up_sync(0xFFFFFFFFu, dn, off);
        float om = __shfl_up_sync(0xFFFFFFFFu, m, off);
        int   ok = __shfl_up_sync(0xFFFFFFFFu, k, off);
        if (lane >= off) {
            float sm = om + (float)k * decL;   // shift prev summary by my span
            float mn = fmaxf(sm, m);
            float ea = __expf(sm - mn);
            float eb = __expf(m - mn);
            n  = ea * on + eb * n;
            dn = ea * od + eb * dn;
            m  = mn;
            k += ok;
        }
    }

    // exclusive prefix: shift inclusive result up by one lane
    float pn = __shfl_up_sync(0xFFFFFFFFu, n, 1);
    float pd = __shfl_up_sync(0xFFFFFFFFu, dn, 1);
    float pm = __shfl_up_sync(0xFFFFFFFFu, m, 1);
    if (lane == 0) { pn = 0.f; pd = 0.f; pm = -1e38f; }
    g_pn[o] = pn;
    g_pd[o] = pd;
    g_pm[o] = pm;
}

__global__ void wkv_passC(const float* __restrict__ time_decay,
                          const float* __restrict__ time_first) {
    int idx = blockIdx.x * blockDim.x + threadIdx.x;
    int d = idx % HD;
    int bc = idx / HD;
    int b = bc % BATCH;
    int seg = bc / BATCH;

    float td = -__expf(time_decay[d]);
    float tf = time_first[d];

    float num = g_pn[idx], den = g_pd[idx], mx = g_pm[idx];
    size_t base = (size_t)b * TLEN * HD + d;

    for (int t = seg * SEGLEN; t < (seg + 1) * SEGLEN; t++) {
        size_t off = base + (size_t)t * HD;
        float kt = g_k[off];
        float vt = g_v[off];
        float rt = g_r[off];

        float mfo = fmaxf(mx, kt + tf);
        float e1  = __expf(mx - mfo);
        float e2  = __expf(kt + tf - mfo);
        float out = (e1 * num + e2 * vt) / (e1 * den + e2);

        float mfs = fmaxf(mx + td, kt);
        float e1s = __expf(mx + td - mfs);
        float e2s = __expf(kt - mfs);
        num = e1s * num + e2s * vt;
        den = e1s * den + e2s;
        mx  = mfs;

        g_ak[off] = __float2half_rn(out * rt);
    }
}

// ---------------------------------------------------------------------------
// Launch
// ---------------------------------------------------------------------------
extern "C" void kernel_launch(void* const* d_in, const int* in_sizes, int n_in,
                              void* d_out, int out_size) {
    const float* hidden = (const float*)d_in[0];
    const float* time_decay = (const float*)d_in[1];
    const float* time_first = (const float*)d_in[2];
    const float* tmk = (const float*)d_in[3];
    const float* tmv = (const float*)d_in[4];
    const float* tmr = (const float*)d_in[5];
    const float* Wk = (const float*)d_in[6];
    const float* Wv = (const float*)d_in[7];
    const float* Wr = (const float*)d_in[8];
    const float* Wo = (const float*)d_in[9];

    __half *ak, *av, *ar, *wk, *wv, *wr, *wo;
    float *kb, *vb, *rb;
    cudaGetSymbolAddress((void**)&ak, g_ak);
    cudaGetSymbolAddress((void**)&av, g_av);
    cudaGetSymbolAddress((void**)&ar, g_ar);
    cudaGetSymbolAddress((void**)&wk, g_wk);
    cudaGetSymbolAddress((void**)&wv, g_wv);
    cudaGetSymbolAddress((void**)&wr, g_wr);
    cudaGetSymbolAddress((void**)&wo, g_wo);
    cudaGetSymbolAddress((void**)&kb, g_k);
    cudaGetSymbolAddress((void**)&vb, g_v);
    cudaGetSymbolAddress((void**)&rb, g_r);

    cudaFuncSetAttribute(gemm_f16, cudaFuncAttributeMaxDynamicSharedMemorySize, SMEM_GEMM);

    // 1. weight transposes (fused, z = matrix index)
    transpose_half4<<<dim3(HD / 32, HD / 32, 4), 256>>>(Wk, Wv, Wr, Wo,
                                                        wk, wv, wr, wo);

    // 2. mixes (fp16 planes)
    mix_kernel<<<(int)(TOT / 4 / 256), 256>>>(hidden, tmk, tmv, tmr);

    // 3. three input GEMMs in ONE launch (z selects k/v/r; z==2 gets sigmoid)
    dim3 grid3(HD / BN, MROWS / BM, 3);   // (16, 64, 3)
    gemm_f16<<<grid3, 256, SMEM_GEMM>>>(ak, av, ar, wk, wv, wr, kb, vb, rb, 2);

    // 4. WKV segmented scan (SEG=32), writes p into g_ak
    wkv_passA<<<SEG * CH / 256, 256>>>(time_decay);
    wkv_passB<<<CH * 32 / 256, 256>>>(time_decay);
    wkv_passC<<<SEG * CH / 256, 256>>>(time_decay, time_first);

    // 5. output GEMM
    dim3 grid1(HD / BN, MROWS / BM, 1);
    gemm_f16<<<grid1, 256, SMEM_GEMM>>>(ak, ak, ak, wo, wo, wo,
                                        (float*)d_out, (float*)d_out,
                                        (float*)d_out, -1);
}

// round 15
// speedup vs baseline: 1.0234x; 1.0072x over previous
#include <cuda_runtime.h>
#include <cuda_fp16.h>
#include <cstdint>
#include <math.h>

// ---------------------------------------------------------------------------
// Problem dims (fixed)
// ---------------------------------------------------------------------------
constexpr int BATCH = 4;
constexpr int TLEN  = 2048;
constexpr int HD    = 2048;                  // N = K = 2048
constexpr int MROWS = BATCH * TLEN;          // 8192
constexpr size_t TOT = (size_t)MROWS * HD;   // 16,777,216
constexpr int CH    = BATCH * HD;            // 8192 scan channels
constexpr int SEG   = 32;
constexpr int SEGLEN = TLEN / SEG;           // 64

// GEMM tiling: CTA 128x128x64, 8 warps (2M x 4N), warp tile 64x32, 3 stages,
// 2 CTAs/SM (smem 110.6 KB, regs <= 128)
constexpr int BM = 128;
constexpr int BN = 128;
constexpr int BK = 64;
constexpr int NITER = HD / BK;               // 32
constexpr int STAGES = 3;
constexpr int PITCH = 144;                   // 64 fp16 = 128B data + 16B pad
constexpr int PLANE = 128 * PITCH;           // 18432
constexpr int STAGE_BYTES = 2 * PLANE;       // A + B = 36864
constexpr int SMEM_GEMM = STAGES * STAGE_BYTES;  // 110592

// ---------------------------------------------------------------------------
// Scratch (device globals: allocation-free per harness rules)
// ---------------------------------------------------------------------------
__device__ __align__(256) __half g_ak[TOT];   // key-mix (reused as p = r*rwkv)
__device__ __align__(256) __half g_av[TOT];
__device__ __align__(256) __half g_ar[TOT];
__device__ __align__(256) __half g_vh[TOT];   // v GEMM output (fp16)
__device__ __align__(256) float g_k[TOT];
__device__ __align__(256) float g_r[TOT];
// transposed weights: [N=2048, K=2048] fp16, K-major
__device__ __align__(256) __half g_wk[HD * HD];
__device__ __align__(256) __half g_wv[HD * HD];
__device__ __align__(256) __half g_wr[HD * HD];
__device__ __align__(256) __half g_wo[HD * HD];
// WKV segment summaries / prefixes: [SEG][CH]
__device__ float g_sn[SEG * CH];
__device__ float g_sd[SEG * CH];
__device__ float g_sm[SEG * CH];
__device__ float g_pn[SEG * CH];
__device__ float g_pd[SEG * CH];
__device__ float g_pm[SEG * CH];

// ---------------------------------------------------------------------------
// PTX helpers (base sm_103 target: cp.async, ldmatrix, mma.sync)
// ---------------------------------------------------------------------------
__device__ __forceinline__ uint32_t smem_u32(const void* p) {
    uint32_t a;
    asm("{ .reg .u64 t; cvta.to.shared.u64 t, %1; cvt.u32.u64 %0, t; }"
        : "=r"(a) : "l"(p));
    return a;
}

__device__ __forceinline__ void cp_async16(uint32_t s, const void* g) {
    asm volatile("cp.async.cg.shared.global [%0], [%1], 16;" :: "r"(s), "l"(g));
}
__device__ __forceinline__ void cp_commit() {
    asm volatile("cp.async.commit_group;" ::: "memory");
}
template <int N>
__device__ __forceinline__ void cp_wait() {
    asm volatile("cp.async.wait_group %0;" :: "n"(N) : "memory");
}

__device__ __forceinline__ void ldsm_x4(uint32_t* r, uint32_t addr) {
    asm volatile("ldmatrix.sync.aligned.m8n8.x4.shared.b16 {%0,%1,%2,%3}, [%4];"
        : "=r"(r[0]), "=r"(r[1]), "=r"(r[2]), "=r"(r[3]) : "r"(addr));
}

// mma.sync m16n8k16 fp16 -> fp32, D += A*B
__device__ __forceinline__ void mma16816(float* d, const uint32_t* a,
                                         uint32_t b0, uint32_t b1) {
    asm volatile(
        "mma.sync.aligned.m16n8k16.row.col.f32.f16.f16.f32 "
        "{%0,%1,%2,%3}, {%4,%5,%6,%7}, {%8,%9}, {%0,%1,%2,%3};"
        : "+f"(d[0]), "+f"(d[1]), "+f"(d[2]), "+f"(d[3])
        : "r"(a[0]), "r"(a[1]), "r"(a[2]), "r"(a[3]), "r"(b0), "r"(b1));
}

__device__ __forceinline__ uint32_t pack2h(__half a, __half b) {
    __half2 t(a, b);
    return *(uint32_t*)&t;
}

// ---------------------------------------------------------------------------
// Fused weight transposes:  W[K,N] fp32 -> T[N,K] fp16  (z selects matrix)
// Tile 64(k) x 32(n); half2 stores for 128B/warp store segments.
// ---------------------------------------------------------------------------
__global__ void transpose_half4(const float* __restrict__ W0,
                                const float* __restrict__ W1,
                                const float* __restrict__ W2,
                                const float* __restrict__ W3,
                                __half* __restrict__ T0,
                                __half* __restrict__ T1,
                                __half* __restrict__ T2,
                                __half* __restrict__ T3) {
    const float* W;
    __half* T;
    switch (blockIdx.z) {
        case 0: W = W0; T = T0; break;
        case 1: W = W1; T = T1; break;
        case 2: W = W2; T = T2; break;
        default: W = W3; T = T3; break;
    }
    __shared__ float tile[64][33];
    int tx = threadIdx.x & 31;
    int ty0 = threadIdx.x >> 5;          // 0..7
    int bx = blockIdx.x * 32;            // n base
    int by = blockIdx.y * 64;            // k base
    #pragma unroll
    for (int i = 0; i < 8; i++)
        tile[ty0 + i * 8][tx] = W[(size_t)(by + ty0 + i * 8) * HD + bx + tx];
    __syncthreads();
    #pragma unroll
    for (int i = 0; i < 4; i++) {
        int n = ty0 + i * 8;             // 0..31
        __half2 o(__float2half_rn(tile[2 * tx][n]),
                  __float2half_rn(tile[2 * tx + 1][n]));
        *(__half2*)(T + (size_t)(bx + n) * HD + by + 2 * tx) = o;
    }
}

// ---------------------------------------------------------------------------
// Time-shift + three mixes -> three fp16 planes
// ---------------------------------------------------------------------------
__global__ void mix_kernel(const float* __restrict__ hidden,
                           const float* __restrict__ tmk,
                           const float* __restrict__ tmv,
                           const float* __restrict__ tmr) {
    int idx = blockIdx.x * blockDim.x + threadIdx.x;  // float4 index
    constexpr int HV = HD / 4;
    int row = idx / HV;
    int hv  = idx % HV;
    bool hasPrev = (row % TLEN) != 0;

    const float4* h4 = (const float4*)hidden;
    float4 cur  = h4[idx];
    float4 prev = hasPrev ? h4[idx - HV] : make_float4(0.f, 0.f, 0.f, 0.f);

    float4 mk = ((const float4*)tmk)[hv];
    float4 mv = ((const float4*)tmv)[hv];
    float4 mr = ((const float4*)tmr)[hv];

    float c[4] = {cur.x, cur.y, cur.z, cur.w};
    float p[4] = {prev.x, prev.y, prev.z, prev.w};
    float k_[4] = {mk.x, mk.y, mk.z, mk.w};
    float v_[4] = {mv.x, mv.y, mv.z, mv.w};
    float r_[4] = {mr.x, mr.y, mr.z, mr.w};

    __half hk[4], hv_[4], hr[4];
    #pragma unroll
    for (int i = 0; i < 4; i++) {
        hk[i]  = __float2half_rn(p[i] + k_[i] * (c[i] - p[i]));
        hv_[i] = __float2half_rn(p[i] + v_[i] * (c[i] - p[i]));
        hr[i]  = __float2half_rn(p[i] + r_[i] * (c[i] - p[i]));
    }

    uint2 out;
    out.x = pack2h(hk[0], hk[1]);  out.y = pack2h(hk[2], hk[3]);
    ((uint2*)g_ak)[idx] = out;
    out.x = pack2h(hv_[0], hv_[1]); out.y = pack2h(hv_[2], hv_[3]);
    ((uint2*)g_av)[idx] = out;
    out.x = pack2h(hr[0], hr[1]);  out.y = pack2h(hr[2], hr[3]);
    ((uint2*)g_ar)[idx] = out;
}

// ---------------------------------------------------------------------------
// fp16 mma.sync GEMM:  C[M,HD] = A[M,HD] @ Bt[HD,HD]^T  (Bt is [N,K] K-major)
// CTA 128x128x64, 8 warps (2M x 4N), warp tile 64x32, 3 stages, 2 CTAs/SM.
// Software-pipelined A fragments (double buffer across k16 steps).
// blockIdx.z selects the (A, B, C) triple. z == sigz: sigmoid epilogue (fp32
// out). z == halfz: plain epilogue but fp16 output (C cast to __half*).
// ---------------------------------------------------------------------------
__global__ void __launch_bounds__(256, 2)
gemm_f16(const __half* __restrict__ A0, const __half* __restrict__ A1,
         const __half* __restrict__ A2,
         const __half* __restrict__ B0, const __half* __restrict__ B1,
         const __half* __restrict__ B2,
         float* __restrict__ C0, float* __restrict__ C1, float* __restrict__ C2,
         int sigz, int halfz) {
    extern __shared__ char smem[];
    uint32_t sbase = smem_u32(smem);

    const __half* A;
    const __half* B;
    float* C;
    int z = blockIdx.z;
    if (z == 0)      { A = A0; B = B0; C = C0; }
    else if (z == 1) { A = A1; B = B1; C = C1; }
    else             { A = A2; B = B2; C = C2; }
    bool sig  = (z == sigz);
    bool halfo = (z == halfz);

    int tid = threadIdx.x;
    int wid = tid >> 5;
    int lid = tid & 31;
    int mBase = blockIdx.y * BM;
    int nBase = blockIdx.x * BN;

    int wm = (wid & 1) * 64;       // warp M offset
    int wn = (wid >> 1) * 32;      // warp N offset

    // gmem->smem: A 1024 chunks(16B) + B 1024 chunks = 2048, 8/thread
    auto load_stage = [&](int buf, int k0) {
        uint32_t st = sbase + buf * STAGE_BYTES;
        #pragma unroll
        for (int i = 0; i < 4; i++) {
            int id = tid + i * 256;
            int r = id >> 3, c = id & 7;
            uint32_t so = (uint32_t)(r * PITCH + c * 16);
            cp_async16(st + so,         A + (size_t)(mBase + r) * HD + k0 + c * 8);
            cp_async16(st + PLANE + so, B + (size_t)(nBase + r) * HD + k0 + c * 8);
        }
    };

    float acc[4][4][4];
    #pragma unroll
    for (int a = 0; a < 4; a++)
        #pragma unroll
        for (int b = 0; b < 4; b++)
            #pragma unroll
            for (int c = 0; c < 4; c++) acc[a][b][c] = 0.f;

    load_stage(0, 0);
    cp_commit();
    load_stage(1, BK);
    cp_commit();

    // A ldmatrix lane address: rows m = wm + (lid&15), byte (lid>>4)*16
    uint32_t aLane = (uint32_t)((wm + (lid & 15)) * PITCH + (lid >> 4) * 16);
    // B ldmatrix lane address (pair p covers fn = 2p, 2p+1)
    uint32_t bLane = (uint32_t)((wn + (lid & 7) + ((lid >> 3) & 1) * 8) * PITCH
                                + (lid >> 4) * 16);

    uint32_t ah[2][4][4];   // double-buffered A frags

    for (int s = 0; s < NITER; s++) {
        cp_wait<STAGES - 2>();
        __syncthreads();

        if (s + STAGES - 1 < NITER) {
            load_stage((s + STAGES - 1) % STAGES, (s + STAGES - 1) * BK);
            cp_commit();
        }

        uint32_t st = sbase + (s % STAGES) * STAGE_BYTES;
        uint32_t aA = st + aLane;
        uint32_t bB = st + PLANE + bLane;

        // preload A frags for ks = 0
        #pragma unroll
        for (int fm = 0; fm < 4; fm++)
            ldsm_x4(ah[0][fm], aA + fm * (16 * PITCH));

        #pragma unroll
        for (int ks = 0; ks < 4; ks++) {     // 4 x k16 per stage
            int cur = ks & 1, nxt = cur ^ 1;
            uint32_t bb[2][4];
            #pragma unroll
            for (int p = 0; p < 2; p++)      // each covers fn = 2p, 2p+1
                ldsm_x4(bb[p], bB + p * (16 * PITCH) + ks * 32);
            if (ks < 3) {                    // prefetch next ks A frags
                #pragma unroll
                for (int fm = 0; fm < 4; fm++)
                    ldsm_x4(ah[nxt][fm], aA + fm * (16 * PITCH) + (ks + 1) * 32);
            }
            #pragma unroll
            for (int fm = 0; fm < 4; fm++)
                #pragma unroll
                for (int p = 0; p < 2; p++) {
                    mma16816(acc[fm][2 * p],     ah[cur][fm], bb[p][0], bb[p][2]);
                    mma16816(acc[fm][2 * p + 1], ah[cur][fm], bb[p][1], bb[p][3]);
                }
        }
    }

    // epilogue
    int gid = lid >> 2, tig = lid & 3;
    if (halfo) {
        __half* Ch = (__half*)C;
        #pragma unroll
        for (int fm = 0; fm < 4; fm++) {
            int row0 = mBase + wm + fm * 16 + gid;
            #pragma unroll
            for (int fn = 0; fn < 4; fn++) {
                int col = nBase + wn + fn * 8 + tig * 2;
                *(__half2*)(Ch + (size_t)row0 * HD + col) =
                    __half2(__float2half_rn(acc[fm][fn][0]),
                            __float2half_rn(acc[fm][fn][1]));
                *(__half2*)(Ch + (size_t)(row0 + 8) * HD + col) =
                    __half2(__float2half_rn(acc[fm][fn][2]),
                            __float2half_rn(acc[fm][fn][3]));
            }
        }
    } else {
        #pragma unroll
        for (int fm = 0; fm < 4; fm++) {
            int row0 = mBase + wm + fm * 16 + gid;
            #pragma unroll
            for (int fn = 0; fn < 4; fn++) {
                int col = nBase + wn + fn * 8 + tig * 2;
                float2 v0 = make_float2(acc[fm][fn][0], acc[fm][fn][1]);
                float2 v1 = make_float2(acc[fm][fn][2], acc[fm][fn][3]);
                if (sig) {
                    v0.x = 1.f / (1.f + __expf(-v0.x));
                    v0.y = 1.f / (1.f + __expf(-v0.y));
                    v1.x = 1.f / (1.f + __expf(-v1.x));
                    v1.y = 1.f / (1.f + __expf(-v1.y));
                }
                *(float2*)(C + (size_t)row0 * HD + col) = v0;
                *(float2*)(C + (size_t)(row0 + 8) * HD + col) = v1;
            }
        }
    }
}

// ---------------------------------------------------------------------------
// WKV 3-phase segmented scan. Channel ch = b*HD + d. idx = seg*CH + ch.
// SEG=32 segments of 64 steps: 262144 threads => latency fully hidden.
// v is fp16 (g_vh); k stays fp32 (exp-sensitive).
// ---------------------------------------------------------------------------
__global__ void wkv_passA(const float* __restrict__ time_decay) {
    int idx = blockIdx.x * blockDim.x + threadIdx.x;   // 0..SEG*CH-1
    int d = idx % HD;
    int bc = idx / HD;
    int b = bc % BATCH;
    int seg = bc / BATCH;

    float td = -__expf(time_decay[d]);
    float num = 0.f, den = 0.f, mx = -1e38f;
    size_t base = (size_t)b * TLEN * HD + d;

    for (int t = seg * SEGLEN; t < (seg + 1) * SEGLEN; t++) {
        size_t off = base + (size_t)t * HD;
        float kt = g_k[off];
        float vt = __half2float(g_vh[off]);
        float mfs = fmaxf(mx + td, kt);
        float e1s = __expf(mx + td - mfs);
        float e2s = __expf(kt - mfs);
        num = e1s * num + e2s * vt;
        den = e1s * den + e2s;
        mx  = mfs;
    }
    g_sn[idx] = num;
    g_sd[idx] = den;
    g_sm[idx] = mx;
}

// Pass B: warp-parallel Kogge-Stone scan over segments. One warp per channel,
// lane = segment.
__global__ void wkv_passB(const float* __restrict__ time_decay) {
    int gtid = blockIdx.x * blockDim.x + threadIdx.x;
    int ch = gtid >> 5;                 // warp index = channel
    int lane = gtid & 31;               // lane = segment
    int d = ch % HD;
    float decL = -__expf(time_decay[d]) * (float)SEGLEN;

    int o = lane * CH + ch;
    float n = g_sn[o], dn = g_sd[o], m = g_sm[o];
    int k = 1;

    #pragma unroll
    for (int off = 1; off < 32; off <<= 1) {
        float on = __shfl_up_sync(0xFFFFFFFFu, n, off);
        float od = __shfl_up_sync(0xFFFFFFFFu, dn, off);
        float om = __shfl_up_sync(0xFFFFFFFFu, m, off);
        int   ok = __shfl_up_sync(0xFFFFFFFFu, k, off);
        if (lane >= off) {
            float sm = om + (float)k * decL;   // shift prev summary by my span
            float mn = fmaxf(sm, m);
            float ea = __expf(sm - mn);
            float eb = __expf(m - mn);
            n  = ea * on + eb * n;
            dn = ea * od + eb * dn;
            m  = mn;
            k += ok;
        }
    }

    // exclusive prefix: shift inclusive result up by one lane
    float pn = __shfl_up_sync(0xFFFFFFFFu, n, 1);
    float pd = __shfl_up_sync(0xFFFFFFFFu, dn, 1);
    float pm = __shfl_up_sync(0xFFFFFFFFu, m, 1);
    if (lane == 0) { pn = 0.f; pd = 0.f; pm = -1e38f; }
    g_pn[o] = pn;
    g_pd[o] = pd;
    g_pm[o] = pm;
}

__global__ void wkv_passC(const float* __restrict__ time_decay,
                          const float* __restrict__ time_first) {
    int idx = blockIdx.x * blockDim.x + threadIdx.x;
    int d = idx % HD;
    int bc = idx / HD;
    int b = bc % BATCH;
    int seg = bc / BATCH;

    float td = -__expf(time_decay[d]);
    float tf = time_first[d];

    float num = g_pn[idx], den = g_pd[idx], mx = g_pm[idx];
    size_t base = (size_t)b * TLEN * HD + d;

    for (int t = seg * SEGLEN; t < (seg + 1) * SEGLEN; t++) {
        size_t off = base + (size_t)t * HD;
        float kt = g_k[off];
        float vt = __half2float(g_vh[off]);
        float rt = g_r[off];

        float mfo = fmaxf(mx, kt + tf);
        float e1  = __expf(mx - mfo);
        float e2  = __expf(kt + tf - mfo);
        float out = (e1 * num + e2 * vt) / (e1 * den + e2);

        float mfs = fmaxf(mx + td, kt);
        float e1s = __expf(mx + td - mfs);
        float e2s = __expf(kt - mfs);
        num = e1s * num + e2s * vt;
        den = e1s * den + e2s;
        mx  = mfs;

        g_ak[off] = __float2half_rn(out * rt);
    }
}

// ---------------------------------------------------------------------------
// Launch
// ---------------------------------------------------------------------------
extern "C" void kernel_launch(void* const* d_in, const int* in_sizes, int n_in,
                              void* d_out, int out_size) {
    const float* hidden = (const float*)d_in[0];
    const float* time_decay = (const float*)d_in[1];
    const float* time_first = (const float*)d_in[2];
    const float* tmk = (const float*)d_in[3];
    const float* tmv = (const float*)d_in[4];
    const float* tmr = (const float*)d_in[5];
    const float* Wk = (const float*)d_in[6];
    const float* Wv = (const float*)d_in[7];
    const float* Wr = (const float*)d_in[8];
    const float* Wo = (const float*)d_in[9];

    __half *ak, *av, *ar, *vh, *wk, *wv, *wr, *wo;
    float *kb, *rb;
    cudaGetSymbolAddress((void**)&ak, g_ak);
    cudaGetSymbolAddress((void**)&av, g_av);
    cudaGetSymbolAddress((void**)&ar, g_ar);
    cudaGetSymbolAddress((void**)&vh, g_vh);
    cudaGetSymbolAddress((void**)&wk, g_wk);
    cudaGetSymbolAddress((void**)&wv, g_wv);
    cudaGetSymbolAddress((void**)&wr, g_wr);
    cudaGetSymbolAddress((void**)&wo, g_wo);
    cudaGetSymbolAddress((void**)&kb, g_k);
    cudaGetSymbolAddress((void**)&rb, g_r);

    cudaFuncSetAttribute(gemm_f16, cudaFuncAttributeMaxDynamicSharedMemorySize, SMEM_GEMM);

    // 1. weight transposes (fused, z = matrix index; 64x32 tiles, half2 stores)
    transpose_half4<<<dim3(HD / 32, HD / 64, 4), 256>>>(Wk, Wv, Wr, Wo,
                                                        wk, wv, wr, wo);

    // 2. mixes (fp16 planes)
    mix_kernel<<<(int)(TOT / 4 / 256), 256>>>(hidden, tmk, tmv, tmr);

    // 3. three input GEMMs in ONE launch
    //    z==1 (v): fp16 output into g_vh; z==2 (r): sigmoid, fp32
    dim3 grid3(HD / BN, MROWS / BM, 3);   // (16, 64, 3)
    gemm_f16<<<grid3, 256, SMEM_GEMM>>>(ak, av, ar, wk, wv, wr,
                                        kb, (float*)vh, rb, 2, 1);

    // 4. WKV segmented scan (SEG=32), writes p into g_ak
    wkv_passA<<<SEG * CH / 256, 256>>>(time_decay);
    wkv_passB<<<CH * 32 / 256, 256>>>(time_decay);
    wkv_passC<<<SEG * CH / 256, 256>>>(time_decay, time_first);

    // 5. output GEMM
    dim3 grid1(HD / BN, MROWS / BM, 1);
    gemm_f16<<<grid1, 256, SMEM_GEMM>>>(ak, ak, ak, wo, wo, wo,
                                        (float*)d_out, (float*)d_out,
                                        (float*)d_out, -1, -1);
}

// round 16
// speedup vs baseline: 1.0296x; 1.0061x over previous
#include <cuda_runtime.h>
#include <cuda_fp16.h>
#include <cstdint>
#include <math.h>

// ---------------------------------------------------------------------------
// Problem dims (fixed)
// ---------------------------------------------------------------------------
constexpr int BATCH = 4;
constexpr int TLEN  = 2048;
constexpr int HD    = 2048;                  // N = K = 2048
constexpr int MROWS = BATCH * TLEN;          // 8192
constexpr size_t TOT = (size_t)MROWS * HD;   // 16,777,216
constexpr int CH    = BATCH * HD;            // 8192 scan channels
constexpr int SEG   = 32;
constexpr int SEGLEN = TLEN / SEG;           // 64

// GEMM tiling: CTA 128x128x64, 8 warps (2M x 4N), warp tile 64x32, 3 stages,
// 2 CTAs/SM (smem 110.6 KB, regs <= 128)
constexpr int BM = 128;
constexpr int BN = 128;
constexpr int BK = 64;
constexpr int NITER = HD / BK;               // 32
constexpr int STAGES = 3;
constexpr int PITCH = 144;                   // 64 fp16 = 128B data + 16B pad
constexpr int PLANE = 128 * PITCH;           // 18432
constexpr int STAGE_BYTES = 2 * PLANE;       // A + B = 36864
constexpr int SMEM_GEMM = STAGES * STAGE_BYTES;  // 110592

// ---------------------------------------------------------------------------
// Scratch (device globals: allocation-free per harness rules)
// ---------------------------------------------------------------------------
__device__ __align__(256) __half g_ak[TOT];   // key-mix (reused as p = r*rwkv)
__device__ __align__(256) __half g_av[TOT];
__device__ __align__(256) __half g_ar[TOT];
__device__ __align__(256) __half g_kh[TOT];   // k GEMM output (fp16)
__device__ __align__(256) __half g_vh[TOT];   // v GEMM output (fp16)
__device__ __align__(256) __half g_rh[TOT];   // r = sigmoid(..) (fp16)
// transposed weights: [N=2048, K=2048] fp16, K-major
__device__ __align__(256) __half g_wk[HD * HD];
__device__ __align__(256) __half g_wv[HD * HD];
__device__ __align__(256) __half g_wr[HD * HD];
__device__ __align__(256) __half g_wo[HD * HD];
// WKV segment summaries / prefixes: [SEG][CH]
__device__ float g_sn[SEG * CH];
__device__ float g_sd[SEG * CH];
__device__ float g_sm[SEG * CH];
__device__ float g_pn[SEG * CH];
__device__ float g_pd[SEG * CH];
__device__ float g_pm[SEG * CH];

// ---------------------------------------------------------------------------
// PTX helpers (base sm_103 target: cp.async, ldmatrix, mma.sync)
// ---------------------------------------------------------------------------
__device__ __forceinline__ uint32_t smem_u32(const void* p) {
    uint32_t a;
    asm("{ .reg .u64 t; cvta.to.shared.u64 t, %1; cvt.u32.u64 %0, t; }"
        : "=r"(a) : "l"(p));
    return a;
}

__device__ __forceinline__ void cp_async16(uint32_t s, const void* g) {
    asm volatile("cp.async.cg.shared.global [%0], [%1], 16;" :: "r"(s), "l"(g));
}
__device__ __forceinline__ void cp_commit() {
    asm volatile("cp.async.commit_group;" ::: "memory");
}
template <int N>
__device__ __forceinline__ void cp_wait() {
    asm volatile("cp.async.wait_group %0;" :: "n"(N) : "memory");
}

__device__ __forceinline__ void ldsm_x4(uint32_t* r, uint32_t addr) {
    asm volatile("ldmatrix.sync.aligned.m8n8.x4.shared.b16 {%0,%1,%2,%3}, [%4];"
        : "=r"(r[0]), "=r"(r[1]), "=r"(r[2]), "=r"(r[3]) : "r"(addr));
}

// mma.sync m16n8k16 fp16 -> fp32, D += A*B
__device__ __forceinline__ void mma16816(float* d, const uint32_t* a,
                                         uint32_t b0, uint32_t b1) {
    asm volatile(
        "mma.sync.aligned.m16n8k16.row.col.f32.f16.f16.f32 "
        "{%0,%1,%2,%3}, {%4,%5,%6,%7}, {%8,%9}, {%0,%1,%2,%3};"
        : "+f"(d[0]), "+f"(d[1]), "+f"(d[2]), "+f"(d[3])
        : "r"(a[0]), "r"(a[1]), "r"(a[2]), "r"(a[3]), "r"(b0), "r"(b1));
}

__device__ __forceinline__ uint32_t pack2h(__half a, __half b) {
    __half2 t(a, b);
    return *(uint32_t*)&t;
}

// ---------------------------------------------------------------------------
// Fused weight transposes:  W[K,N] fp32 -> T[N,K] fp16  (z selects matrix)
// Tile 64(k) x 32(n); half2 stores for 128B/warp store segments.
// ---------------------------------------------------------------------------
__global__ void transpose_half4(const float* __restrict__ W0,
                                const float* __restrict__ W1,
                                const float* __restrict__ W2,
                                const float* __restrict__ W3,
                                __half* __restrict__ T0,
                                __half* __restrict__ T1,
                                __half* __restrict__ T2,
                                __half* __restrict__ T3) {
    const float* W;
    __half* T;
    switch (blockIdx.z) {
        case 0: W = W0; T = T0; break;
        case 1: W = W1; T = T1; break;
        case 2: W = W2; T = T2; break;
        default: W = W3; T = T3; break;
    }
    __shared__ float tile[64][33];
    int tx = threadIdx.x & 31;
    int ty0 = threadIdx.x >> 5;          // 0..7
    int bx = blockIdx.x * 32;            // n base
    int by = blockIdx.y * 64;            // k base
    #pragma unroll
    for (int i = 0; i < 8; i++)
        tile[ty0 + i * 8][tx] = W[(size_t)(by + ty0 + i * 8) * HD + bx + tx];
    __syncthreads();
    #pragma unroll
    for (int i = 0; i < 4; i++) {
        int n = ty0 + i * 8;             // 0..31
        __half2 o(__float2half_rn(tile[2 * tx][n]),
                  __float2half_rn(tile[2 * tx + 1][n]));
        *(__half2*)(T + (size_t)(bx + n) * HD + by + 2 * tx) = o;
    }
}

// ---------------------------------------------------------------------------
// Time-shift + three mixes -> three fp16 planes
// ---------------------------------------------------------------------------
__global__ void mix_kernel(const float* __restrict__ hidden,
                           const float* __restrict__ tmk,
                           const float* __restrict__ tmv,
                           const float* __restrict__ tmr) {
    int idx = blockIdx.x * blockDim.x + threadIdx.x;  // float4 index
    constexpr int HV = HD / 4;
    int row = idx / HV;
    int hv  = idx % HV;
    bool hasPrev = (row % TLEN) != 0;

    const float4* h4 = (const float4*)hidden;
    float4 cur  = h4[idx];
    float4 prev = hasPrev ? h4[idx - HV] : make_float4(0.f, 0.f, 0.f, 0.f);

    float4 mk = ((const float4*)tmk)[hv];
    float4 mv = ((const float4*)tmv)[hv];
    float4 mr = ((const float4*)tmr)[hv];

    float c[4] = {cur.x, cur.y, cur.z, cur.w};
    float p[4] = {prev.x, prev.y, prev.z, prev.w};
    float k_[4] = {mk.x, mk.y, mk.z, mk.w};
    float v_[4] = {mv.x, mv.y, mv.z, mv.w};
    float r_[4] = {mr.x, mr.y, mr.z, mr.w};

    __half hk[4], hv_[4], hr[4];
    #pragma unroll
    for (int i = 0; i < 4; i++) {
        hk[i]  = __float2half_rn(p[i] + k_[i] * (c[i] - p[i]));
        hv_[i] = __float2half_rn(p[i] + v_[i] * (c[i] - p[i]));
        hr[i]  = __float2half_rn(p[i] + r_[i] * (c[i] - p[i]));
    }

    uint2 out;
    out.x = pack2h(hk[0], hk[1]);  out.y = pack2h(hk[2], hk[3]);
    ((uint2*)g_ak)[idx] = out;
    out.x = pack2h(hv_[0], hv_[1]); out.y = pack2h(hv_[2], hv_[3]);
    ((uint2*)g_av)[idx] = out;
    out.x = pack2h(hr[0], hr[1]);  out.y = pack2h(hr[2], hr[3]);
    ((uint2*)g_ar)[idx] = out;
}

// ---------------------------------------------------------------------------
// fp16 mma.sync GEMM:  C[M,HD] = A[M,HD] @ Bt[HD,HD]^T  (Bt is [N,K] K-major)
// CTA 128x128x64, 8 warps (2M x 4N), warp tile 64x32, 3 stages, 2 CTAs/SM.
// Software-pipelined A fragments (double buffer across k16 steps).
// blockIdx.z selects the (A, B, C) triple. z == sigz: sigmoid before store.
// (halfmask >> z) & 1: store fp16 (C cast to __half*), else fp32.
// ---------------------------------------------------------------------------
__global__ void __launch_bounds__(256, 2)
gemm_f16(const __half* __restrict__ A0, const __half* __restrict__ A1,
         const __half* __restrict__ A2,
         const __half* __restrict__ B0, const __half* __restrict__ B1,
         const __half* __restrict__ B2,
         float* __restrict__ C0, float* __restrict__ C1, float* __restrict__ C2,
         int sigz, int halfmask) {
    extern __shared__ char smem[];
    uint32_t sbase = smem_u32(smem);

    const __half* A;
    const __half* B;
    float* C;
    int z = blockIdx.z;
    if (z == 0)      { A = A0; B = B0; C = C0; }
    else if (z == 1) { A = A1; B = B1; C = C1; }
    else             { A = A2; B = B2; C = C2; }
    bool sig   = (z == sigz);
    bool halfo = ((halfmask >> z) & 1) != 0;

    int tid = threadIdx.x;
    int wid = tid >> 5;
    int lid = tid & 31;
    int mBase = blockIdx.y * BM;
    int nBase = blockIdx.x * BN;

    int wm = (wid & 1) * 64;       // warp M offset
    int wn = (wid >> 1) * 32;      // warp N offset

    // gmem->smem: A 1024 chunks(16B) + B 1024 chunks = 2048, 8/thread
    auto load_stage = [&](int buf, int k0) {
        uint32_t st = sbase + buf * STAGE_BYTES;
        #pragma unroll
        for (int i = 0; i < 4; i++) {
            int id = tid + i * 256;
            int r = id >> 3, c = id & 7;
            uint32_t so = (uint32_t)(r * PITCH + c * 16);
            cp_async16(st + so,         A + (size_t)(mBase + r) * HD + k0 + c * 8);
            cp_async16(st + PLANE + so, B + (size_t)(nBase + r) * HD + k0 + c * 8);
        }
    };

    float acc[4][4][4];
    #pragma unroll
    for (int a = 0; a < 4; a++)
        #pragma unroll
        for (int b = 0; b < 4; b++)
            #pragma unroll
            for (int c = 0; c < 4; c++) acc[a][b][c] = 0.f;

    load_stage(0, 0);
    cp_commit();
    load_stage(1, BK);
    cp_commit();

    // A ldmatrix lane address: rows m = wm + (lid&15), byte (lid>>4)*16
    uint32_t aLane = (uint32_t)((wm + (lid & 15)) * PITCH + (lid >> 4) * 16);
    // B ldmatrix lane address (pair p covers fn = 2p, 2p+1)
    uint32_t bLane = (uint32_t)((wn + (lid & 7) + ((lid >> 3) & 1) * 8) * PITCH
                                + (lid >> 4) * 16);

    uint32_t ah[2][4][4];   // double-buffered A frags

    for (int s = 0; s < NITER; s++) {
        cp_wait<STAGES - 2>();
        __syncthreads();

        if (s + STAGES - 1 < NITER) {
            load_stage((s + STAGES - 1) % STAGES, (s + STAGES - 1) * BK);
            cp_commit();
        }

        uint32_t st = sbase + (s % STAGES) * STAGE_BYTES;
        uint32_t aA = st + aLane;
        uint32_t bB = st + PLANE + bLane;

        // preload A frags for ks = 0
        #pragma unroll
        for (int fm = 0; fm < 4; fm++)
            ldsm_x4(ah[0][fm], aA + fm * (16 * PITCH));

        #pragma unroll
        for (int ks = 0; ks < 4; ks++) {     // 4 x k16 per stage
            int cur = ks & 1, nxt = cur ^ 1;
            uint32_t bb[2][4];
            #pragma unroll
            for (int p = 0; p < 2; p++)      // each covers fn = 2p, 2p+1
                ldsm_x4(bb[p], bB + p * (16 * PITCH) + ks * 32);
            if (ks < 3) {                    // prefetch next ks A frags
                #pragma unroll
                for (int fm = 0; fm < 4; fm++)
                    ldsm_x4(ah[nxt][fm], aA + fm * (16 * PITCH) + (ks + 1) * 32);
            }
            #pragma unroll
            for (int fm = 0; fm < 4; fm++)
                #pragma unroll
                for (int p = 0; p < 2; p++) {
                    mma16816(acc[fm][2 * p],     ah[cur][fm], bb[p][0], bb[p][2]);
                    mma16816(acc[fm][2 * p + 1], ah[cur][fm], bb[p][1], bb[p][3]);
                }
        }
    }

    // epilogue
    int gid = lid >> 2, tig = lid & 3;
    #pragma unroll
    for (int fm = 0; fm < 4; fm++) {
        int row0 = mBase + wm + fm * 16 + gid;
        #pragma unroll
        for (int fn = 0; fn < 4; fn++) {
            int col = nBase + wn + fn * 8 + tig * 2;
            float a0 = acc[fm][fn][0], a1 = acc[fm][fn][1];
            float a2 = acc[fm][fn][2], a3 = acc[fm][fn][3];
            if (sig) {
                a0 = 1.f / (1.f + __expf(-a0));
                a1 = 1.f / (1.f + __expf(-a1));
                a2 = 1.f / (1.f + __expf(-a2));
                a3 = 1.f / (1.f + __expf(-a3));
            }
            if (halfo) {
                __half* Ch = (__half*)C;
                *(__half2*)(Ch + (size_t)row0 * HD + col) =
                    __half2(__float2half_rn(a0), __float2half_rn(a1));
                *(__half2*)(Ch + (size_t)(row0 + 8) * HD + col) =
                    __half2(__float2half_rn(a2), __float2half_rn(a3));
            } else {
                *(float2*)(C + (size_t)row0 * HD + col) = make_float2(a0, a1);
                *(float2*)(C + (size_t)(row0 + 8) * HD + col) = make_float2(a2, a3);
            }
        }
    }
}

// ---------------------------------------------------------------------------
// WKV 3-phase segmented scan. Channel ch = b*HD + d. idx = seg*CH + ch.
// SEG=32 segments of 64 steps. k, v, r all fp16 in gmem; fp32 state.
// ---------------------------------------------------------------------------
__global__ void wkv_passA(const float* __restrict__ time_decay) {
    int idx = blockIdx.x * blockDim.x + threadIdx.x;   // 0..SEG*CH-1
    int d = idx % HD;
    int bc = idx / HD;
    int b = bc % BATCH;
    int seg = bc / BATCH;

    float td = -__expf(time_decay[d]);
    float num = 0.f, den = 0.f, mx = -1e38f;
    size_t base = (size_t)b * TLEN * HD + d;

    for (int t = seg * SEGLEN; t < (seg + 1) * SEGLEN; t++) {
        size_t off = base + (size_t)t * HD;
        float kt = __half2float(g_kh[off]);
        float vt = __half2float(g_vh[off]);
        float mfs = fmaxf(mx + td, kt);
        float e1s = __expf(mx + td - mfs);
        float e2s = __expf(kt - mfs);
        num = e1s * num + e2s * vt;
        den = e1s * den + e2s;
        mx  = mfs;
    }
    g_sn[idx] = num;
    g_sd[idx] = den;
    g_sm[idx] = mx;
}

// Pass B: warp-parallel Kogge-Stone scan over segments. One warp per channel,
// lane = segment.
__global__ void wkv_passB(const float* __restrict__ time_decay) {
    int gtid = blockIdx.x * blockDim.x + threadIdx.x;
    int ch = gtid >> 5;                 // warp index = channel
    int lane = gtid & 31;               // lane = segment
    int d = ch % HD;
    float decL = -__expf(time_decay[d]) * (float)SEGLEN;

    int o = lane * CH + ch;
    float n = g_sn[o], dn = g_sd[o], m = g_sm[o];
    int k = 1;

    #pragma unroll
    for (int off = 1; off < 32; off <<= 1) {
        float on = __shfl_up_sync(0xFFFFFFFFu, n, off);
        float od = __shfl_up_sync(0xFFFFFFFFu, dn, off);
        float om = __shfl_up_sync(0xFFFFFFFFu, m, off);
        int   ok = __shfl_up_sync(0xFFFFFFFFu, k, off);
        if (lane >= off) {
            float sm = om + (float)k * decL;   // shift prev summary by my span
            float mn = fmaxf(sm, m);
            float ea = __expf(sm - mn);
            float eb = __expf(m - mn);
            n  = ea * on + eb * n;
            dn = ea * od + eb * dn;
            m  = mn;
            k += ok;
        }
    }

    // exclusive prefix: shift inclusive result up by one lane
    float pn = __shfl_up_sync(0xFFFFFFFFu, n, 1);
    float pd = __shfl_up_sync(0xFFFFFFFFu, dn, 1);
    float pm = __shfl_up_sync(0xFFFFFFFFu, m, 1);
    if (lane == 0) { pn = 0.f; pd = 0.f; pm = -1e38f; }
    g_pn[o] = pn;
    g_pd[o] = pd;
    g_pm[o] = pm;
}

__global__ void wkv_passC(const float* __restrict__ time_decay,
                          const float* __restrict__ time_first) {
    int idx = blockIdx.x * blockDim.x + threadIdx.x;
    int d = idx % HD;
    int bc = idx / HD;
    int b = bc % BATCH;
    int seg = bc / BATCH;

    float td = -__expf(time_decay[d]);
    float tf = time_first[d];

    float num = g_pn[idx], den = g_pd[idx], mx = g_pm[idx];
    size_t base = (size_t)b * TLEN * HD + d;

    for (int t = seg * SEGLEN; t < (seg + 1) * SEGLEN; t++) {
        size_t off = base + (size_t)t * HD;
        float kt = __half2float(g_kh[off]);
        float vt = __half2float(g_vh[off]);
        float rt = __half2float(g_rh[off]);

        float mfo = fmaxf(mx, kt + tf);
        float e1  = __expf(mx - mfo);
        float e2  = __expf(kt + tf - mfo);
        float out = (e1 * num + e2 * vt) / (e1 * den + e2);

        float mfs = fmaxf(mx + td, kt);
        float e1s = __expf(mx + td - mfs);
        float e2s = __expf(kt - mfs);
        num = e1s * num + e2s * vt;
        den = e1s * den + e2s;
        mx  = mfs;

        g_ak[off] = __float2half_rn(out * rt);
    }
}

// ---------------------------------------------------------------------------
// Launch
// ---------------------------------------------------------------------------
extern "C" void kernel_launch(void* const* d_in, const int* in_sizes, int n_in,
                              void* d_out, int out_size) {
    const float* hidden = (const float*)d_in[0];
    const float* time_decay = (const float*)d_in[1];
    const float* time_first = (const float*)d_in[2];
    const float* tmk = (const float*)d_in[3];
    const float* tmv = (const float*)d_in[4];
    const float* tmr = (const float*)d_in[5];
    const float* Wk = (const float*)d_in[6];
    const float* Wv = (const float*)d_in[7];
    const float* Wr = (const float*)d_in[8];
    const float* Wo = (const float*)d_in[9];

    __half *ak, *av, *ar, *kh, *vh, *rh, *wk, *wv, *wr, *wo;
    cudaGetSymbolAddress((void**)&ak, g_ak);
    cudaGetSymbolAddress((void**)&av, g_av);
    cudaGetSymbolAddress((void**)&ar, g_ar);
    cudaGetSymbolAddress((void**)&kh, g_kh);
    cudaGetSymbolAddress((void**)&vh, g_vh);
    cudaGetSymbolAddress((void**)&rh, g_rh);
    cudaGetSymbolAddress((void**)&wk, g_wk);
    cudaGetSymbolAddress((void**)&wv, g_wv);
    cudaGetSymbolAddress((void**)&wr, g_wr);
    cudaGetSymbolAddress((void**)&wo, g_wo);

    cudaFuncSetAttribute(gemm_f16, cudaFuncAttributeMaxDynamicSharedMemorySize, SMEM_GEMM);

    // 1. weight transposes (fused, z = matrix index; 64x32 tiles, half2 stores)
    transpose_half4<<<dim3(HD / 32, HD / 64, 4), 256>>>(Wk, Wv, Wr, Wo,
                                                        wk, wv, wr, wo);

    // 2. mixes (fp16 planes)
    mix_kernel<<<(int)(TOT / 4 / 256), 256>>>(hidden, tmk, tmv, tmr);

    // 3. three input GEMMs in ONE launch; all outputs fp16 (halfmask=7),
    //    z==2 (r) gets sigmoid before the fp16 store
    dim3 grid3(HD / BN, MROWS / BM, 3);   // (16, 64, 3)
    gemm_f16<<<grid3, 256, SMEM_GEMM>>>(ak, av, ar, wk, wv, wr,
                                        (float*)kh, (float*)vh, (float*)rh,
                                        2, 7);

    // 4. WKV segmented scan (SEG=32), writes p into g_ak
    wkv_passA<<<SEG * CH / 256, 256>>>(time_decay);
    wkv_passB<<<CH * 32 / 256, 256>>>(time_decay);
    wkv_passC<<<SEG * CH / 256, 256>>>(time_decay, time_first);

    // 5. output GEMM (fp32 out to d_out)
    dim3 grid1(HD / BN, MROWS / BM, 1);
    gemm_f16<<<grid1, 256, SMEM_GEMM>>>(ak, ak, ak, wo, wo, wo,
                                        (float*)d_out, (float*)d_out,
                                        (float*)d_out, -1, 0);
}